// round 7
// baseline (speedup 1.0000x reference)
#include <cuda_runtime.h>

// Problem constants
#define B_    2
#define T_    2048
#define C_    2048
#define NH_   16
#define HS_   128
#define NLQ_  512
#define NLKV_ 512
#define DHR_  64

#define KCAT  576   // 512 + 64 concatenated K for fused S GEMM

// ---------------------------------------------------------------------------
// Static scratch
// ---------------------------------------------------------------------------
__device__ float g_xt  [B_*T_*C_];              // tf32-rounded x
__device__ float g_wdq [NLQ_*C_];
__device__ float g_wuq [C_*NLQ_];
__device__ float g_wdkv[NLKV_*C_];
__device__ float g_wuk [C_*NLKV_];
__device__ float g_wuv [C_*NLKV_];
__device__ float g_wqr [NH_*DHR_*NLQ_];
__device__ float g_wo  [C_*C_];

__device__ float g_cq  [B_*T_*NLQ_];
__device__ float g_ckv [B_*T_*KCAT];            // [b,t, 0:512]=c_kv, [512:576]=k_r
__device__ float g_keff[NH_*NLQ_*NLKV_];
__device__ float g_Rt  [C_*NLKV_];
__device__ float g_qc  [B_*NH_*T_*KCAT];        // [.., 0:512]=q_c, [512:576]=q_r
__device__ float g_cqr [B_*T_*NH_*DHR_];
__device__ float g_ckr [B_*T_*DHR_];
__device__ float g_S   [134217728];             // 512 MB [B,NH,T,T]
__device__ float g_ctx [B_*NH_*T_*NLKV_];

// ---------------------------------------------------------------------------
__device__ __forceinline__ float ftf32(float x) {
    unsigned u;
    asm("cvt.rna.tf32.f32 %0, %1;" : "=r"(u) : "f"(x));
    return __uint_as_float(u);
}

__device__ __forceinline__ void mma_tf32(float* c, const unsigned* a, const unsigned* b) {
    asm volatile(
        "mma.sync.aligned.m16n8k8.row.col.f32.tf32.tf32.f32 "
        "{%0,%1,%2,%3},{%4,%5,%6,%7},{%8,%9},{%0,%1,%2,%3};\n"
        : "+f"(c[0]), "+f"(c[1]), "+f"(c[2]), "+f"(c[3])
        : "r"(a[0]), "r"(a[1]), "r"(a[2]), "r"(a[3]), "r"(b[0]), "r"(b[1]));
}

__device__ __forceinline__ void cp16(float* dst, const float* src) {
    unsigned d = (unsigned)__cvta_generic_to_shared(dst);
    asm volatile("cp.async.cg.shared.global [%0], [%1], 16;\n" :: "r"(d), "l"(src));
}

// ---------------------------------------------------------------------------
// TF32 tensor-core batched GEMM: C[m,n] = sum_k A[m,k] * B'[k,n]
//   BT==1: B' = B^T (B row-major [N,K]); BT==0: B' = B row-major [K,N].
//   CTA tile 256(M) x 128(N) x 32(K), 3-stage cp.async pipeline,
//   8 warps (4m x 2n), warp tile 64x64 = 4x8 m16n8k8 fragments.
//   Requires M%256==0, N%128==0, K%32==0.
//   causal bit1: skip CTA if cols entirely above diagonal (bx >= 2*by+2)
//   causal bit0: cap K loop at row0+256 (P columns beyond are zero)
// ---------------------------------------------------------------------------
#define AS_F  (256 * 36)             // 9216 floats
#define BS_F  (128 * 36)             // 4608 floats (NN needs 32*136=4352 <= this)
#define STG_F (AS_F + BS_F)          // 13824 floats per stage

__global__ void __launch_bounds__(256) tf32gemm(
    const float* __restrict__ A, const float* __restrict__ B, float* __restrict__ C,
    int K, int lda, int ldb, int ldc, int HB,
    long long sAb, long long sAh,
    long long sBb, long long sBh,
    long long sCb, long long sCh,
    int BT, int rnd, int causal)
{
    if ((causal & 2) && ((int)blockIdx.x >= 2 * (int)blockIdx.y + 2)) return;

    extern __shared__ float sm[];

    const int z  = blockIdx.z;
    const int bb = z / HB, hh = z - bb * HB;
    A += bb * sAb + hh * sAh;
    B += bb * sBb + hh * sBh;
    C += bb * sCb + hh * sCh;

    const int row0 = blockIdx.y * 256;
    const int col0 = blockIdx.x * 128;

    const int tid  = threadIdx.x;
    const int warp = tid >> 5, lane = tid & 31;
    const int wm = warp >> 1, wn = warp & 1;     // 4(m) x 2(n) warps
    const int g  = lane >> 2, t = lane & 3;

    const int lr = tid >> 3;     // 0..31 (row within a 32-row group)
    const int kq = tid & 7;      // float4 slot along k
    const int nr = tid >> 5;     // 0..7  (k-row group, NN-B)
    const int nq = tid & 31;     // float4 slot along n (NN-B)

    float acc[4][8][4];
    #pragma unroll
    for (int i = 0; i < 4; i++)
        #pragma unroll
        for (int j = 0; j < 8; j++)
            #pragma unroll
            for (int q = 0; q < 4; q++) acc[i][j][q] = 0.f;

    int nk = K >> 5;
    if (causal & 1) {
        int cap = (row0 + 256) >> 5;
        if (cap < nk) nk = cap;
    }

    // As: [m 0..255][k 0..31] stride 36
    // Bs (BT): [n 0..127][k 0..31] stride 36 ; Bs (NN): [k 0..31][n 0..127] stride 136
#define ISSUE(KT)                                                                         \
    do {                                                                                  \
        if ((KT) < nk) {                                                                  \
            const int k0_ = (KT) * 32;                                                    \
            float* As_ = sm + ((KT) % 3) * STG_F;                                         \
            float* Bs_ = As_ + AS_F;                                                      \
            _Pragma("unroll")                                                             \
            for (int i = 0; i < 8; i++)                                                   \
                cp16(As_ + (i * 32 + lr) * 36 + kq * 4,                                   \
                     A + (long long)(row0 + i * 32 + lr) * lda + k0_ + kq * 4);           \
            _Pragma("unroll")                                                             \
            for (int i = 0; i < 4; i++) {                                                 \
                if (BT)                                                                   \
                    cp16(Bs_ + (i * 32 + lr) * 36 + kq * 4,                               \
                         B + (long long)(col0 + i * 32 + lr) * ldb + k0_ + kq * 4);       \
                else                                                                      \
                    cp16(Bs_ + (i * 8 + nr) * 136 + nq * 4,                               \
                         B + (long long)(k0_ + i * 8 + nr) * ldb + col0 + nq * 4);        \
            }                                                                             \
        }                                                                                 \
        asm volatile("cp.async.commit_group;\n");                                        \
    } while (0)

    ISSUE(0);
    ISSUE(1);

    for (int kt = 0; kt < nk; kt++) {
        ISSUE(kt + 2);
        asm volatile("cp.async.wait_group 2;\n" ::: "memory");
        __syncthreads();

        const float* As = sm + (kt % 3) * STG_F;
        const float* Bs = As + AS_F;

        #pragma unroll
        for (int kk = 0; kk < 32; kk += 8) {
            unsigned af[4][4], bf[8][2];
            #pragma unroll
            for (int i = 0; i < 4; i++) {
                int r = wm * 64 + i * 16 + g;
                af[i][0] = __float_as_uint(As[r * 36 + kk + t]);
                af[i][1] = __float_as_uint(As[(r + 8) * 36 + kk + t]);
                af[i][2] = __float_as_uint(As[r * 36 + kk + t + 4]);
                af[i][3] = __float_as_uint(As[(r + 8) * 36 + kk + t + 4]);
            }
            #pragma unroll
            for (int j = 0; j < 8; j++) {
                int c = wn * 64 + j * 8 + g;
                if (BT) {
                    bf[j][0] = __float_as_uint(Bs[c * 36 + kk + t]);
                    bf[j][1] = __float_as_uint(Bs[c * 36 + kk + t + 4]);
                } else {
                    bf[j][0] = __float_as_uint(Bs[(kk + t) * 136 + c]);
                    bf[j][1] = __float_as_uint(Bs[(kk + t + 4) * 136 + c]);
                }
            }
            #pragma unroll
            for (int i = 0; i < 4; i++)
                #pragma unroll
                for (int j = 0; j < 8; j++)
                    mma_tf32(acc[i][j], af[i], bf[j]);
        }
        __syncthreads();
    }
#undef ISSUE

    // Epilogue
    #pragma unroll
    for (int i = 0; i < 4; i++) {
        long long r0 = row0 + wm * 64 + i * 16 + g;
        #pragma unroll
        for (int j = 0; j < 8; j++) {
            int cc = col0 + wn * 64 + j * 8 + 2 * t;
            float v0 = acc[i][j][0], v1 = acc[i][j][1];
            float v2 = acc[i][j][2], v3 = acc[i][j][3];
            if (rnd) { v0 = ftf32(v0); v1 = ftf32(v1); v2 = ftf32(v2); v3 = ftf32(v3); }
            *(float2*)(C + r0 * ldc + cc)       = make_float2(v0, v1);
            *(float2*)(C + (r0 + 8) * ldc + cc) = make_float2(v2, v3);
        }
    }
}

// ---------------------------------------------------------------------------
// Elementwise round-to-tf32
// ---------------------------------------------------------------------------
__global__ void round_tf32_kernel(const float* __restrict__ in, float* __restrict__ out, int n4)
{
    int i = blockIdx.x * 256 + threadIdx.x;
    if (i >= n4) return;
    float4 v = ((const float4*)in)[i];
    v.x = ftf32(v.x); v.y = ftf32(v.y); v.z = ftf32(v.z); v.w = ftf32(v.w);
    ((float4*)out)[i] = v;
}

// ---------------------------------------------------------------------------
// SIMT SGEMM fallback (only the tiny c_kr projection, full fp32)
// ---------------------------------------------------------------------------
__global__ void sgemm64(const float* __restrict__ A, const float* __restrict__ B,
                        float* __restrict__ C,
                        int M, int N, int K, int lda, int ldb, int ldc)
{
    const int row0 = blockIdx.y * 64;
    const int col0 = blockIdx.x * 64;

    __shared__ float As[16][68];
    __shared__ float Bs[16][68];

    const int tid = threadIdx.x;
    const int tx  = tid & 15;
    const int ty  = tid >> 4;
    const int ar = tid >> 2;
    const int ak = (tid & 3) * 4;

    float acc[4][4] = {};

    for (int k0 = 0; k0 < K; k0 += 16) {
        float4 av = *(const float4*)(A + (long long)(row0 + ar) * lda + (k0 + ak));
        As[ak + 0][ar] = av.x;
        As[ak + 1][ar] = av.y;
        As[ak + 2][ar] = av.z;
        As[ak + 3][ar] = av.w;
        float4 bv = *(const float4*)(B + (long long)(col0 + ar) * ldb + (k0 + ak)); // B^T
        Bs[ak + 0][ar] = bv.x;
        Bs[ak + 1][ar] = bv.y;
        Bs[ak + 2][ar] = bv.z;
        Bs[ak + 3][ar] = bv.w;
        __syncthreads();

        #pragma unroll
        for (int kk = 0; kk < 16; kk++) {
            float4 a4 = *(const float4*)&As[kk][ty * 4];
            float4 b4 = *(const float4*)&Bs[kk][tx * 4];
            float aa[4] = {a4.x, a4.y, a4.z, a4.w};
            float bbv[4] = {b4.x, b4.y, b4.z, b4.w};
            #pragma unroll
            for (int i = 0; i < 4; i++)
                #pragma unroll
                for (int j = 0; j < 4; j++)
                    acc[i][j] += aa[i] * bbv[j];
        }
        __syncthreads();
    }

    #pragma unroll
    for (int i = 0; i < 4; i++)
        #pragma unroll
        for (int j = 0; j < 4; j++)
            C[(long long)(row0 + ty * 4 + i) * ldc + (col0 + tx * 4 + j)] = acc[i][j];
}

// ---------------------------------------------------------------------------
// RoPE kernels (outputs tf32-rounded, written into concatenated buffers)
// ---------------------------------------------------------------------------
__global__ void rope_q_kernel(const float* __restrict__ in, float* __restrict__ qcbuf,
                              const float* __restrict__ cosp, const float* __restrict__ sinp)
{
    int j = blockIdx.x * blockDim.x + threadIdx.x;
    if (j >= B_ * T_ * NH_ * (DHR_ / 2)) return;
    int i = j & 31;
    int h = (j >> 5) & 15;
    int t = (j >> 9) & 2047;
    int b = j >> 20;
    float c = cosp[t * 32 + i];
    float s = sinp[t * 32 + i];
    float re = in[2 * j], im = in[2 * j + 1];
    long long base = ((long long)(b * NH_ + h) * T_ + t) * KCAT + 512 + 2 * i;
    qcbuf[base]     = ftf32(re * c - im * s);
    qcbuf[base + 1] = ftf32(re * s + im * c);
}

__global__ void rope_k_kernel(const float* __restrict__ in, float* __restrict__ ckvbuf,
                              const float* __restrict__ cosp, const float* __restrict__ sinp)
{
    int j = blockIdx.x * blockDim.x + threadIdx.x;
    if (j >= B_ * T_ * (DHR_ / 2)) return;
    int i = j & 31;
    int t = (j >> 5) & 2047;
    int b = j >> 16;
    float c = cosp[t * 32 + i];
    float s = sinp[t * 32 + i];
    float re = in[2 * j], im = in[2 * j + 1];
    long long base = ((long long)b * T_ + t) * KCAT + 512 + 2 * i;
    ckvbuf[base]     = ftf32(re * c - im * s);
    ckvbuf[base + 1] = ftf32(re * s + im * c);
}

// ---------------------------------------------------------------------------
// Causal softmax, in-place, tf32-rounded output. One block per row.
// Writes cols [0, ceil256(t+1)) — exactly what the 256-row-capped ctx GEMM reads.
// ---------------------------------------------------------------------------
__global__ void softmax_causal_kernel(float* __restrict__ S)
{
    const float scale = 0.07216878364870323f;   // 1/sqrt(192)
    long long row = blockIdx.x;
    int t = (int)(row % T_);
    int limit = ((t >> 8) + 1) << 8;            // multiple of 256 covering t
    float* p = S + row * (long long)T_;
    int tid = threadIdx.x;

    float v[8];
    float m = -3.0e38f;
    #pragma unroll
    for (int j = 0; j < 8; j++) {
        int i = tid + j * 256;
        float x = -3.0e38f;
        if (i <= t) x = p[i] * scale;
        v[j] = x;
        m = fmaxf(m, x);
    }

    __shared__ float red[256];
    red[tid] = m;
    __syncthreads();
    for (int s = 128; s > 0; s >>= 1) {
        if (tid < s) red[tid] = fmaxf(red[tid], red[tid + s]);
        __syncthreads();
    }
    m = red[0];
    __syncthreads();

    float sum = 0.f;
    #pragma unroll
    for (int j = 0; j < 8; j++) {
        int i = tid + j * 256;
        float e = (i <= t) ? __expf(v[j] - m) : 0.f;
        v[j] = e;
        sum += e;
    }
    red[tid] = sum;
    __syncthreads();
    for (int s = 128; s > 0; s >>= 1) {
        if (tid < s) red[tid] += red[tid + s];
        __syncthreads();
    }
    float inv = 1.0f / red[0];

    #pragma unroll
    for (int j = 0; j < 8; j++) {
        int i = tid + j * 256;
        if (i < limit) p[i] = ftf32(v[j] * inv);
    }
}

// ---------------------------------------------------------------------------
// Host
// ---------------------------------------------------------------------------
#define SMEM_BYTES (3 * STG_F * 4)   // 165888

static inline void launch_tf32(const float* A, const float* B, float* C,
                               int M, int N, int K, int lda, int ldb, int ldc,
                               int batches, int HB,
                               long long sAb, long long sAh,
                               long long sBb, long long sBh,
                               long long sCb, long long sCh,
                               int BT, int rnd, int causal)
{
    dim3 grid(N / 128, M / 256, batches);
    tf32gemm<<<grid, 256, SMEM_BYTES>>>(A, B, C, K, lda, ldb, ldc, HB,
                                        sAb, sAh, sBb, sBh, sCb, sCh, BT, rnd, causal);
}

static inline void round_tf32(const float* in, float* out, long long n)
{
    int n4 = (int)(n / 4);
    round_tf32_kernel<<<(n4 + 255) / 256, 256>>>(in, out, n4);
}

extern "C" void kernel_launch(void* const* d_in, const int* in_sizes, int n_in,
                              void* d_out, int out_size)
{
    (void)in_sizes; (void)n_in; (void)out_size;
    const float* x     = (const float*)d_in[0];
    const float* cosp  = (const float*)d_in[1];
    const float* sinp  = (const float*)d_in[2];
    const float* W_dq  = (const float*)d_in[3];
    const float* W_uq  = (const float*)d_in[4];
    const float* W_dkv = (const float*)d_in[5];
    const float* W_uk  = (const float*)d_in[6];
    const float* W_uv  = (const float*)d_in[7];
    const float* W_qr  = (const float*)d_in[8];
    const float* W_kr  = (const float*)d_in[9];
    const float* W_o   = (const float*)d_in[10];
    float* y = (float*)d_out;

    static int smem_set = 0;
    if (!smem_set) {
        cudaFuncSetAttribute(tf32gemm, cudaFuncAttributeMaxDynamicSharedMemorySize, SMEM_BYTES);
        smem_set = 1;
    }

    float *xt, *wdq, *wuq, *wdkv, *wuk, *wuv, *wqr, *wo;
    float *cq, *ckv, *keff, *Rt, *qc, *cqr, *ckr, *S, *ctx;
    cudaGetSymbolAddress((void**)&xt,   g_xt);
    cudaGetSymbolAddress((void**)&wdq,  g_wdq);
    cudaGetSymbolAddress((void**)&wuq,  g_wuq);
    cudaGetSymbolAddress((void**)&wdkv, g_wdkv);
    cudaGetSymbolAddress((void**)&wuk,  g_wuk);
    cudaGetSymbolAddress((void**)&wuv,  g_wuv);
    cudaGetSymbolAddress((void**)&wqr,  g_wqr);
    cudaGetSymbolAddress((void**)&wo,   g_wo);
    cudaGetSymbolAddress((void**)&cq,   g_cq);
    cudaGetSymbolAddress((void**)&ckv,  g_ckv);
    cudaGetSymbolAddress((void**)&keff, g_keff);
    cudaGetSymbolAddress((void**)&Rt,   g_Rt);
    cudaGetSymbolAddress((void**)&qc,   g_qc);
    cudaGetSymbolAddress((void**)&cqr,  g_cqr);
    cudaGetSymbolAddress((void**)&ckr,  g_ckr);
    cudaGetSymbolAddress((void**)&S,    g_S);
    cudaGetSymbolAddress((void**)&ctx,  g_ctx);

    const long long TT    = (long long)T_ * T_;
    const long long T512  = (long long)T_ * 512;
    const long long TKC   = (long long)T_ * KCAT;

    // 0) tf32-round raw inputs
    round_tf32(x,     xt,   (long long)B_*T_*C_);
    round_tf32(W_dq,  wdq,  (long long)NLQ_*C_);
    round_tf32(W_uq,  wuq,  (long long)C_*NLQ_);
    round_tf32(W_dkv, wdkv, (long long)NLKV_*C_);
    round_tf32(W_uk,  wuk,  (long long)C_*NLKV_);
    round_tf32(W_uv,  wuv,  (long long)C_*NLKV_);
    round_tf32(W_qr,  wqr,  (long long)NH_*DHR_*NLQ_);
    round_tf32(W_o,   wo,   (long long)C_*C_);

    // 1) c_q = x @ W_dq^T   [4096,512]   (rounded out)
    launch_tf32(xt, wdq, cq, B_*T_, NLQ_, C_, C_, C_, NLQ_,
                1, 1, 0,0, 0,0, 0,0, 1, 1, 0);
    // 2) c_kv = x @ W_dkv^T [4096,512] -> ckv buffer (ldc=576, rounded)
    launch_tf32(xt, wdkv, ckv, B_*T_, NLKV_, C_, C_, C_, KCAT,
                1, 1, 0,0, 0,0, 0,0, 1, 1, 0);
    // 3) k_eff[h] (16 batched, 512x512x128, rounded)
    launch_tf32(wuq, wuk, keff, NLQ_, NLKV_, HS_, C_, NLKV_, NLKV_,
                NH_, NH_, 0, HS_, 0, (long long)HS_*NLKV_, 0, (long long)NLQ_*NLKV_, 0, 1, 0);
    // 4) Rt = W_o @ W_uv    [2048,512]   (rounded)
    launch_tf32(wo, wuv, Rt, C_, NLKV_, C_, C_, NLKV_, NLKV_,
                1, 1, 0,0, 0,0, 0,0, 0, 1, 0);
    // 5) q_c[b,h] = c_q[b] @ k_eff[h] -> qc buffer (ldc=576, rounded)
    launch_tf32(cq, keff, qc, T_, NLKV_, NLQ_, NLQ_, NLKV_, KCAT,
                B_*NH_, NH_, T512, 0, 0, (long long)NLQ_*NLKV_,
                (long long)NH_*TKC, TKC, 0, 1, 0);
    // 6) c_qr = c_q @ W_qr^T [4096,1024] (rope rounds later)
    launch_tf32(cq, wqr, cqr, B_*T_, NH_*DHR_, NLQ_, NLQ_, NLQ_, NH_*DHR_,
                1, 1, 0,0, 0,0, 0,0, 1, 0, 0);
    // 7) q_r = rope(c_qr) -> qc buffer cols [512:576]
    {
        int n = B_ * T_ * NH_ * (DHR_ / 2);
        rope_q_kernel<<<(n + 255) / 256, 256>>>(cqr, qc, cosp, sinp);
    }
    // 8) c_kr = x @ W_kr^T  [4096,64] (SIMT, full fp32)
    {
        dim3 grid(DHR_ / 64, (B_*T_) / 64, 1);
        sgemm64<<<grid, 256>>>(x, W_kr, ckr, B_*T_, DHR_, C_, C_, C_, DHR_);
    }
    // 9) k_r = rope(c_kr) -> ckv buffer cols [512:576]
    {
        int n = B_ * T_ * (DHR_ / 2);
        rope_k_kernel<<<(n + 255) / 256, 256>>>(ckr, ckv, cosp, sinp);
    }
    // 10) S = [q_c|q_r] @ [c_kv|k_r]^T  (32 batched, 2048x2048x576, causal-skip)
    launch_tf32(qc, ckv, S, T_, T_, KCAT, KCAT, KCAT, T_,
                B_*NH_, NH_, (long long)NH_*TKC, TKC, TKC, 0,
                (long long)NH_*TT, TT, 1, 0, 2);
    // 12) causal softmax in place (rounded, trimmed to ceil256(t+1) cols)
    softmax_causal_kernel<<<B_*NH_*T_, 256>>>(S);
    // 13) ctx = P @ c_kv    (32 batched, 2048x512x2048, K capped at row0+256)
    launch_tf32(S, ckv, ctx, T_, NLKV_, T_, T_, KCAT, NLKV_,
                B_*NH_, NH_, (long long)NH_*TT, TT, TKC, 0,
                (long long)NH_*T512, T512, 0, 1, 1);
    // 14) y = ctx[b,h] @ Rt[h*128:,:]^T (32 batched, 2048x128x512)
    launch_tf32(ctx, Rt, y, T_, HS_, NLKV_, NLKV_, NLKV_, C_,
                B_*NH_, NH_, (long long)NH_*T512, T512, 0, (long long)HS_*NLKV_,
                (long long)T_*C_, HS_, 1, 0, 0);
}

// round 8
// speedup vs baseline: 1.0820x; 1.0820x over previous
#include <cuda_runtime.h>

// Problem constants
#define B_    2
#define T_    2048
#define C_    2048
#define NH_   16
#define HS_   128
#define NLQ_  512
#define NLKV_ 512
#define DHR_  64

#define KCAT  576   // 512 + 64 concatenated K for fused S GEMM

// ---------------------------------------------------------------------------
// Static scratch
// ---------------------------------------------------------------------------
__device__ float g_xt  [B_*T_*C_];              // tf32-rounded x
__device__ float g_wdq [NLQ_*C_];
__device__ float g_wuq [C_*NLQ_];
__device__ float g_wdkv[NLKV_*C_];
__device__ float g_wuk [C_*NLKV_];
__device__ float g_wuv [C_*NLKV_];
__device__ float g_wqr [NH_*DHR_*NLQ_];
__device__ float g_wo  [C_*C_];

__device__ float g_cq  [B_*T_*NLQ_];
__device__ float g_ckv [B_*T_*KCAT];            // [b,t, 0:512]=c_kv, [512:576]=k_r
__device__ float g_keff[NH_*NLQ_*NLKV_];
__device__ float g_Rt  [C_*NLKV_];
__device__ float g_qc  [B_*NH_*T_*KCAT];        // [.., 0:512]=q_c, [512:576]=q_r
__device__ float g_cqr [B_*T_*NH_*DHR_];
__device__ float g_ckr [B_*T_*DHR_];
__device__ float g_S   [134217728];             // 512 MB [B,NH,T,T]
__device__ float g_ctx [B_*NH_*T_*NLKV_];

// ---------------------------------------------------------------------------
__device__ __forceinline__ float ftf32(float x) {
    unsigned u;
    asm("cvt.rna.tf32.f32 %0, %1;" : "=r"(u) : "f"(x));
    return __uint_as_float(u);
}

__device__ __forceinline__ void mma_tf32(float* c, const unsigned* a, const unsigned* b) {
    asm volatile(
        "mma.sync.aligned.m16n8k8.row.col.f32.tf32.tf32.f32 "
        "{%0,%1,%2,%3},{%4,%5,%6,%7},{%8,%9},{%0,%1,%2,%3};\n"
        : "+f"(c[0]), "+f"(c[1]), "+f"(c[2]), "+f"(c[3])
        : "r"(a[0]), "r"(a[1]), "r"(a[2]), "r"(a[3]), "r"(b[0]), "r"(b[1]));
}

__device__ __forceinline__ void cp16(float* dst, const float* src) {
    unsigned d = (unsigned)__cvta_generic_to_shared(dst);
    asm volatile("cp.async.cg.shared.global [%0], [%1], 16;\n" :: "r"(d), "l"(src));
}

// ---------------------------------------------------------------------------
// TF32 tensor-core batched GEMM: C[m,n] = sum_k A[m,k] * B'[k,n]
//   BT==1: B' = B^T (B row-major [N,K]); BT==0: B' = B row-major [K,N].
//   CTA 128x128x32, 3-stage cp.async pipeline, 8 warps (4m x 2n),
//   SINGLE barrier per k-tile: wait_group 1 + bar publishes stage kt AND
//   proves stage (kt-1)%3 — the one ISSUE(kt+2) overwrites — is drained.
//   causal bit1: skip CTA entirely if col0 > row0 (upper-triangle tile)
//   causal bit0: cap K loop at row0+128 (P columns beyond are zero)
// ---------------------------------------------------------------------------
#define STG_F 9216   // floats per stage (As 4608 + Bs 4608)

__global__ void __launch_bounds__(256, 2) tf32gemm(
    const float* __restrict__ A, const float* __restrict__ B, float* __restrict__ C,
    int K, int lda, int ldb, int ldc, int HB,
    long long sAb, long long sAh,
    long long sBb, long long sBh,
    long long sCb, long long sCh,
    int BT, int rnd, int causal)
{
    if ((causal & 2) && (blockIdx.x > blockIdx.y)) return;

    extern __shared__ float sm[];

    const int z  = blockIdx.z;
    const int bb = z / HB, hh = z - bb * HB;
    A += bb * sAb + hh * sAh;
    B += bb * sBb + hh * sBh;
    C += bb * sCb + hh * sCh;

    const int row0 = blockIdx.y * 128;
    const int col0 = blockIdx.x * 128;

    const int tid  = threadIdx.x;
    const int warp = tid >> 5, lane = tid & 31;
    const int wm = warp >> 1, wn = warp & 1;
    const int g  = lane >> 2, t = lane & 3;

    const int lr = tid >> 3;     // 0..31
    const int kq = tid & 7;      // float4 slot along k
    const int nr = tid >> 5;     // 0..7
    const int nq = tid & 31;     // float4 slot along n

    float acc[2][8][4];
    #pragma unroll
    for (int i = 0; i < 2; i++)
        #pragma unroll
        for (int j = 0; j < 8; j++)
            #pragma unroll
            for (int q = 0; q < 4; q++) acc[i][j][q] = 0.f;

    int nk = K >> 5;
    if (causal & 1) {
        int cap = (row0 + 128) >> 5;
        if (cap < nk) nk = cap;
    }

    // As: [m][k] stride 36 ; Bs(BT): [n][k] stride 36 ; Bs(NN): [k][n] stride 136
#define ISSUE(KT)                                                                         \
    do {                                                                                  \
        if ((KT) < nk) {                                                                  \
            const int k0_ = (KT) * 32;                                                    \
            float* As_ = sm + ((KT) % 3) * STG_F;                                         \
            float* Bs_ = As_ + 4608;                                                      \
            _Pragma("unroll")                                                             \
            for (int i = 0; i < 4; i++) {                                                 \
                cp16(As_ + (i * 32 + lr) * 36 + kq * 4,                                   \
                     A + (long long)(row0 + i * 32 + lr) * lda + k0_ + kq * 4);           \
                if (BT)                                                                   \
                    cp16(Bs_ + (i * 32 + lr) * 36 + kq * 4,                               \
                         B + (long long)(col0 + i * 32 + lr) * ldb + k0_ + kq * 4);       \
                else                                                                      \
                    cp16(Bs_ + (i * 8 + nr) * 136 + nq * 4,                               \
                         B + (long long)(k0_ + i * 8 + nr) * ldb + col0 + nq * 4);        \
            }                                                                             \
        }                                                                                 \
        asm volatile("cp.async.commit_group;\n");                                        \
    } while (0)

    ISSUE(0);
    ISSUE(1);

    for (int kt = 0; kt < nk; kt++) {
        // Complete stage kt (leave the one younger group in flight), then one
        // barrier: publishes stage kt to all warps AND guarantees all warps
        // finished compute on stage kt-1, which ISSUE(kt+2) reuses.
        asm volatile("cp.async.wait_group 1;\n" ::: "memory");
        __syncthreads();
        ISSUE(kt + 2);

        const float* As = sm + (kt % 3) * STG_F;
        const float* Bs = As + 4608;

        #pragma unroll
        for (int kk = 0; kk < 32; kk += 8) {
            unsigned af[2][4], bf[8][2];
            #pragma unroll
            for (int i = 0; i < 2; i++) {
                int r = wm * 32 + i * 16 + g;
                af[i][0] = __float_as_uint(As[r * 36 + kk + t]);
                af[i][1] = __float_as_uint(As[(r + 8) * 36 + kk + t]);
                af[i][2] = __float_as_uint(As[r * 36 + kk + t + 4]);
                af[i][3] = __float_as_uint(As[(r + 8) * 36 + kk + t + 4]);
            }
            #pragma unroll
            for (int j = 0; j < 8; j++) {
                int c = wn * 64 + j * 8 + g;
                if (BT) {
                    bf[j][0] = __float_as_uint(Bs[c * 36 + kk + t]);
                    bf[j][1] = __float_as_uint(Bs[c * 36 + kk + t + 4]);
                } else {
                    bf[j][0] = __float_as_uint(Bs[(kk + t) * 136 + c]);
                    bf[j][1] = __float_as_uint(Bs[(kk + t + 4) * 136 + c]);
                }
            }
            #pragma unroll
            for (int i = 0; i < 2; i++)
                #pragma unroll
                for (int j = 0; j < 8; j++)
                    mma_tf32(acc[i][j], af[i], bf[j]);
        }
    }
#undef ISSUE

    // Epilogue
    #pragma unroll
    for (int i = 0; i < 2; i++) {
        long long r0 = row0 + wm * 32 + i * 16 + g;
        #pragma unroll
        for (int j = 0; j < 8; j++) {
            int cc = col0 + wn * 64 + j * 8 + 2 * t;
            float v0 = acc[i][j][0], v1 = acc[i][j][1];
            float v2 = acc[i][j][2], v3 = acc[i][j][3];
            if (rnd) { v0 = ftf32(v0); v1 = ftf32(v1); v2 = ftf32(v2); v3 = ftf32(v3); }
            *(float2*)(C + r0 * ldc + cc)       = make_float2(v0, v1);
            *(float2*)(C + (r0 + 8) * ldc + cc) = make_float2(v2, v3);
        }
    }
}

// ---------------------------------------------------------------------------
// Elementwise round-to-tf32
// ---------------------------------------------------------------------------
__global__ void round_tf32_kernel(const float* __restrict__ in, float* __restrict__ out, int n4)
{
    int i = blockIdx.x * 256 + threadIdx.x;
    if (i >= n4) return;
    float4 v = ((const float4*)in)[i];
    v.x = ftf32(v.x); v.y = ftf32(v.y); v.z = ftf32(v.z); v.w = ftf32(v.w);
    ((float4*)out)[i] = v;
}

// ---------------------------------------------------------------------------
// SIMT SGEMM fallback (only the tiny c_kr projection, full fp32)
// ---------------------------------------------------------------------------
__global__ void sgemm64(const float* __restrict__ A, const float* __restrict__ B,
                        float* __restrict__ C,
                        int M, int N, int K, int lda, int ldb, int ldc)
{
    const int row0 = blockIdx.y * 64;
    const int col0 = blockIdx.x * 64;

    __shared__ float As[16][68];
    __shared__ float Bs[16][68];

    const int tid = threadIdx.x;
    const int tx  = tid & 15;
    const int ty  = tid >> 4;
    const int ar = tid >> 2;
    const int ak = (tid & 3) * 4;

    float acc[4][4] = {};

    for (int k0 = 0; k0 < K; k0 += 16) {
        float4 av = *(const float4*)(A + (long long)(row0 + ar) * lda + (k0 + ak));
        As[ak + 0][ar] = av.x;
        As[ak + 1][ar] = av.y;
        As[ak + 2][ar] = av.z;
        As[ak + 3][ar] = av.w;
        float4 bv = *(const float4*)(B + (long long)(col0 + ar) * ldb + (k0 + ak)); // B^T
        Bs[ak + 0][ar] = bv.x;
        Bs[ak + 1][ar] = bv.y;
        Bs[ak + 2][ar] = bv.z;
        Bs[ak + 3][ar] = bv.w;
        __syncthreads();

        #pragma unroll
        for (int kk = 0; kk < 16; kk++) {
            float4 a4 = *(const float4*)&As[kk][ty * 4];
            float4 b4 = *(const float4*)&Bs[kk][tx * 4];
            float aa[4] = {a4.x, a4.y, a4.z, a4.w};
            float bbv[4] = {b4.x, b4.y, b4.z, b4.w};
            #pragma unroll
            for (int i = 0; i < 4; i++)
                #pragma unroll
                for (int j = 0; j < 4; j++)
                    acc[i][j] += aa[i] * bbv[j];
        }
        __syncthreads();
    }

    #pragma unroll
    for (int i = 0; i < 4; i++)
        #pragma unroll
        for (int j = 0; j < 4; j++)
            C[(long long)(row0 + ty * 4 + i) * ldc + (col0 + tx * 4 + j)] = acc[i][j];
}

// ---------------------------------------------------------------------------
// RoPE kernels (outputs tf32-rounded, written into concatenated buffers)
// ---------------------------------------------------------------------------
__global__ void rope_q_kernel(const float* __restrict__ in, float* __restrict__ qcbuf,
                              const float* __restrict__ cosp, const float* __restrict__ sinp)
{
    int j = blockIdx.x * blockDim.x + threadIdx.x;
    if (j >= B_ * T_ * NH_ * (DHR_ / 2)) return;
    int i = j & 31;
    int h = (j >> 5) & 15;
    int t = (j >> 9) & 2047;
    int b = j >> 20;
    float c = cosp[t * 32 + i];
    float s = sinp[t * 32 + i];
    float re = in[2 * j], im = in[2 * j + 1];
    long long base = ((long long)(b * NH_ + h) * T_ + t) * KCAT + 512 + 2 * i;
    qcbuf[base]     = ftf32(re * c - im * s);
    qcbuf[base + 1] = ftf32(re * s + im * c);
}

__global__ void rope_k_kernel(const float* __restrict__ in, float* __restrict__ ckvbuf,
                              const float* __restrict__ cosp, const float* __restrict__ sinp)
{
    int j = blockIdx.x * blockDim.x + threadIdx.x;
    if (j >= B_ * T_ * (DHR_ / 2)) return;
    int i = j & 31;
    int t = (j >> 5) & 2047;
    int b = j >> 16;
    float c = cosp[t * 32 + i];
    float s = sinp[t * 32 + i];
    float re = in[2 * j], im = in[2 * j + 1];
    long long base = ((long long)b * T_ + t) * KCAT + 512 + 2 * i;
    ckvbuf[base]     = ftf32(re * c - im * s);
    ckvbuf[base + 1] = ftf32(re * s + im * c);
}

// ---------------------------------------------------------------------------
// Causal softmax, in-place, tf32-rounded output. One block per row.
// Only touches cols [0, ceil128(t+1)) — exactly what the capped ctx GEMM reads.
// ---------------------------------------------------------------------------
__global__ void softmax_causal_kernel(float* __restrict__ S)
{
    const float scale = 0.07216878364870323f;   // 1/sqrt(192)
    long long row = blockIdx.x;
    int t = (int)(row % T_);
    int limit = ((t >> 7) + 1) << 7;            // multiple of 128 covering t
    float* p = S + row * (long long)T_;
    int tid = threadIdx.x;

    float v[8];
    float m = -3.0e38f;
    #pragma unroll
    for (int j = 0; j < 8; j++) {
        int i = tid + j * 256;
        float x = -3.0e38f;
        if (i <= t) x = p[i] * scale;
        v[j] = x;
        m = fmaxf(m, x);
    }

    __shared__ float red[256];
    red[tid] = m;
    __syncthreads();
    for (int s = 128; s > 0; s >>= 1) {
        if (tid < s) red[tid] = fmaxf(red[tid], red[tid + s]);
        __syncthreads();
    }
    m = red[0];
    __syncthreads();

    float sum = 0.f;
    #pragma unroll
    for (int j = 0; j < 8; j++) {
        int i = tid + j * 256;
        float e = (i <= t) ? __expf(v[j] - m) : 0.f;
        v[j] = e;
        sum += e;
    }
    red[tid] = sum;
    __syncthreads();
    for (int s = 128; s > 0; s >>= 1) {
        if (tid < s) red[tid] += red[tid + s];
        __syncthreads();
    }
    float inv = 1.0f / red[0];

    #pragma unroll
    for (int j = 0; j < 8; j++) {
        int i = tid + j * 256;
        if (i < limit) p[i] = ftf32(v[j] * inv);
    }
}

// ---------------------------------------------------------------------------
// Host
// ---------------------------------------------------------------------------
#define SMEM_BYTES (3 * STG_F * 4)   // 110592

static inline void launch_tf32(const float* A, const float* B, float* C,
                               int M, int N, int K, int lda, int ldb, int ldc,
                               int batches, int HB,
                               long long sAb, long long sAh,
                               long long sBb, long long sBh,
                               long long sCb, long long sCh,
                               int BT, int rnd, int causal)
{
    dim3 grid(N / 128, M / 128, batches);
    tf32gemm<<<grid, 256, SMEM_BYTES>>>(A, B, C, K, lda, ldb, ldc, HB,
                                        sAb, sAh, sBb, sBh, sCb, sCh, BT, rnd, causal);
}

static inline void round_tf32(const float* in, float* out, long long n)
{
    int n4 = (int)(n / 4);
    round_tf32_kernel<<<(n4 + 255) / 256, 256>>>(in, out, n4);
}

extern "C" void kernel_launch(void* const* d_in, const int* in_sizes, int n_in,
                              void* d_out, int out_size)
{
    (void)in_sizes; (void)n_in; (void)out_size;
    const float* x     = (const float*)d_in[0];
    const float* cosp  = (const float*)d_in[1];
    const float* sinp  = (const float*)d_in[2];
    const float* W_dq  = (const float*)d_in[3];
    const float* W_uq  = (const float*)d_in[4];
    const float* W_dkv = (const float*)d_in[5];
    const float* W_uk  = (const float*)d_in[6];
    const float* W_uv  = (const float*)d_in[7];
    const float* W_qr  = (const float*)d_in[8];
    const float* W_kr  = (const float*)d_in[9];
    const float* W_o   = (const float*)d_in[10];
    float* y = (float*)d_out;

    static int smem_set = 0;
    if (!smem_set) {
        cudaFuncSetAttribute(tf32gemm, cudaFuncAttributeMaxDynamicSharedMemorySize, SMEM_BYTES);
        smem_set = 1;
    }

    float *xt, *wdq, *wuq, *wdkv, *wuk, *wuv, *wqr, *wo;
    float *cq, *ckv, *keff, *Rt, *qc, *cqr, *ckr, *S, *ctx;
    cudaGetSymbolAddress((void**)&xt,   g_xt);
    cudaGetSymbolAddress((void**)&wdq,  g_wdq);
    cudaGetSymbolAddress((void**)&wuq,  g_wuq);
    cudaGetSymbolAddress((void**)&wdkv, g_wdkv);
    cudaGetSymbolAddress((void**)&wuk,  g_wuk);
    cudaGetSymbolAddress((void**)&wuv,  g_wuv);
    cudaGetSymbolAddress((void**)&wqr,  g_wqr);
    cudaGetSymbolAddress((void**)&wo,   g_wo);
    cudaGetSymbolAddress((void**)&cq,   g_cq);
    cudaGetSymbolAddress((void**)&ckv,  g_ckv);
    cudaGetSymbolAddress((void**)&keff, g_keff);
    cudaGetSymbolAddress((void**)&Rt,   g_Rt);
    cudaGetSymbolAddress((void**)&qc,   g_qc);
    cudaGetSymbolAddress((void**)&cqr,  g_cqr);
    cudaGetSymbolAddress((void**)&ckr,  g_ckr);
    cudaGetSymbolAddress((void**)&S,    g_S);
    cudaGetSymbolAddress((void**)&ctx,  g_ctx);

    const long long TT    = (long long)T_ * T_;
    const long long T512  = (long long)T_ * 512;
    const long long TKC   = (long long)T_ * KCAT;

    // 0) tf32-round raw inputs
    round_tf32(x,     xt,   (long long)B_*T_*C_);
    round_tf32(W_dq,  wdq,  (long long)NLQ_*C_);
    round_tf32(W_uq,  wuq,  (long long)C_*NLQ_);
    round_tf32(W_dkv, wdkv, (long long)NLKV_*C_);
    round_tf32(W_uk,  wuk,  (long long)C_*NLKV_);
    round_tf32(W_uv,  wuv,  (long long)C_*NLKV_);
    round_tf32(W_qr,  wqr,  (long long)NH_*DHR_*NLQ_);
    round_tf32(W_o,   wo,   (long long)C_*C_);

    // 1) c_q = x @ W_dq^T   [4096,512]   (rounded out)
    launch_tf32(xt, wdq, cq, B_*T_, NLQ_, C_, C_, C_, NLQ_,
                1, 1, 0,0, 0,0, 0,0, 1, 1, 0);
    // 2) c_kv = x @ W_dkv^T [4096,512] -> ckv buffer (ldc=576, rounded)
    launch_tf32(xt, wdkv, ckv, B_*T_, NLKV_, C_, C_, C_, KCAT,
                1, 1, 0,0, 0,0, 0,0, 1, 1, 0);
    // 3) k_eff[h] (16 batched, 512x512x128, rounded)
    launch_tf32(wuq, wuk, keff, NLQ_, NLKV_, HS_, C_, NLKV_, NLKV_,
                NH_, NH_, 0, HS_, 0, (long long)HS_*NLKV_, 0, (long long)NLQ_*NLKV_, 0, 1, 0);
    // 4) Rt = W_o @ W_uv    [2048,512]   (rounded)
    launch_tf32(wo, wuv, Rt, C_, NLKV_, C_, C_, NLKV_, NLKV_,
                1, 1, 0,0, 0,0, 0,0, 0, 1, 0);
    // 5) q_c[b,h] = c_q[b] @ k_eff[h] -> qc buffer (ldc=576, rounded)
    launch_tf32(cq, keff, qc, T_, NLKV_, NLQ_, NLQ_, NLKV_, KCAT,
                B_*NH_, NH_, T512, 0, 0, (long long)NLQ_*NLKV_,
                (long long)NH_*TKC, TKC, 0, 1, 0);
    // 6) c_qr = c_q @ W_qr^T [4096,1024] (rope rounds later)
    launch_tf32(cq, wqr, cqr, B_*T_, NH_*DHR_, NLQ_, NLQ_, NLQ_, NH_*DHR_,
                1, 1, 0,0, 0,0, 0,0, 1, 0, 0);
    // 7) q_r = rope(c_qr) -> qc buffer cols [512:576]
    {
        int n = B_ * T_ * NH_ * (DHR_ / 2);
        rope_q_kernel<<<(n + 255) / 256, 256>>>(cqr, qc, cosp, sinp);
    }
    // 8) c_kr = x @ W_kr^T  [4096,64] (SIMT, full fp32)
    {
        dim3 grid(DHR_ / 64, (B_*T_) / 64, 1);
        sgemm64<<<grid, 256>>>(x, W_kr, ckr, B_*T_, DHR_, C_, C_, C_, DHR_);
    }
    // 9) k_r = rope(c_kr) -> ckv buffer cols [512:576]
    {
        int n = B_ * T_ * (DHR_ / 2);
        rope_k_kernel<<<(n + 255) / 256, 256>>>(ckr, ckv, cosp, sinp);
    }
    // 10) S = [q_c|q_r] @ [c_kv|k_r]^T  (32 batched, 2048x2048x576, causal-skip)
    launch_tf32(qc, ckv, S, T_, T_, KCAT, KCAT, KCAT, T_,
                B_*NH_, NH_, (long long)NH_*TKC, TKC, TKC, 0,
                (long long)NH_*TT, TT, 1, 0, 2);
    // 12) causal softmax in place (rounded, trimmed to ceil128(t+1) cols)
    softmax_causal_kernel<<<B_*NH_*T_, 256>>>(S);
    // 13) ctx = P @ c_kv    (32 batched, 2048x512x2048, K capped at row0+128)
    launch_tf32(S, ckv, ctx, T_, NLKV_, T_, T_, KCAT, NLKV_,
                B_*NH_, NH_, (long long)NH_*TT, TT, TKC, 0,
                (long long)NH_*T512, T512, 0, 1, 1);
    // 14) y = ctx[b,h] @ Rt[h*128:,:]^T (32 batched, 2048x128x512)
    launch_tf32(ctx, Rt, y, T_, HS_, NLKV_, NLKV_, NLKV_, C_,
                B_*NH_, NH_, (long long)NH_*T512, T512, 0, (long long)HS_*NLKV_,
                (long long)T_*C_, HS_, 1, 0, 0);
}

// round 9
// speedup vs baseline: 1.3845x; 1.2796x over previous
#include <cuda_runtime.h>

// Problem constants
#define B_    2
#define T_    2048
#define C_    2048
#define NH_   16
#define HS_   128
#define NLQ_  512
#define NLKV_ 512
#define DHR_  64

#define KCAT  576   // 512 + 64 concatenated K for fused S GEMM

// ---------------------------------------------------------------------------
// Static scratch
// ---------------------------------------------------------------------------
__device__ float g_xt  [B_*T_*C_];              // tf32-rounded x
__device__ float g_wdq [NLQ_*C_];
__device__ float g_wuq [C_*NLQ_];
__device__ float g_wdkv[NLKV_*C_];
__device__ float g_wuk [C_*NLKV_];
__device__ float g_wuv [C_*NLKV_];
__device__ float g_wqr [NH_*DHR_*NLQ_];
__device__ float g_wo  [C_*C_];

__device__ float g_cq  [B_*T_*NLQ_];
__device__ float g_ckv [B_*T_*KCAT];            // [b,t, 0:512]=c_kv, [512:576]=k_r
__device__ float g_keff[NH_*NLQ_*NLKV_];
__device__ float g_Rt  [C_*NLKV_];
__device__ float g_qc  [B_*NH_*T_*KCAT];        // [.., 0:512]=q_c, [512:576]=q_r
__device__ float g_cqr [B_*T_*NH_*DHR_];
__device__ float g_ckr [B_*T_*DHR_];
__device__ float g_S   [134217728];             // 512 MB [B,NH,T,T]
__device__ float g_V   [B_*T_*C_];              // 32 MB: V[b] = c_kv[b] @ Rt^T

// ---------------------------------------------------------------------------
__device__ __forceinline__ float ftf32(float x) {
    unsigned u;
    asm("cvt.rna.tf32.f32 %0, %1;" : "=r"(u) : "f"(x));
    return __uint_as_float(u);
}

__device__ __forceinline__ void mma_tf32(float* c, const unsigned* a, const unsigned* b) {
    asm volatile(
        "mma.sync.aligned.m16n8k8.row.col.f32.tf32.tf32.f32 "
        "{%0,%1,%2,%3},{%4,%5,%6,%7},{%8,%9},{%0,%1,%2,%3};\n"
        : "+f"(c[0]), "+f"(c[1]), "+f"(c[2]), "+f"(c[3])
        : "r"(a[0]), "r"(a[1]), "r"(a[2]), "r"(a[3]), "r"(b[0]), "r"(b[1]));
}

__device__ __forceinline__ void cp16(float* dst, const float* src) {
    unsigned d = (unsigned)__cvta_generic_to_shared(dst);
    asm volatile("cp.async.cg.shared.global [%0], [%1], 16;\n" :: "r"(d), "l"(src));
}

// ---------------------------------------------------------------------------
// TF32 tensor-core batched GEMM (R6-verified mainloop): C[m,n] = A @ B'
//   BT==1: B' = B^T (B row-major [N,K]); BT==0: B' = B row-major [K,N].
//   CTA 128x128x32, 3-stage cp.async pipeline, 8 warps (4m x 2n).
//   causal bit1: skip CTA entirely if col0 > row0 (upper-triangle tile)
//   causal bit0: cap K loop at row0+128 (P columns beyond are zero)
// ---------------------------------------------------------------------------
#define STG_F 9216   // floats per stage (As 4608 + Bs 4608)

__global__ void __launch_bounds__(256, 2) tf32gemm(
    const float* __restrict__ A, const float* __restrict__ B, float* __restrict__ C,
    int K, int lda, int ldb, int ldc, int HB,
    long long sAb, long long sAh,
    long long sBb, long long sBh,
    long long sCb, long long sCh,
    int BT, int rnd, int causal)
{
    if ((causal & 2) && (blockIdx.x > blockIdx.y)) return;

    extern __shared__ float sm[];

    const int z  = blockIdx.z;
    const int bb = z / HB, hh = z - bb * HB;
    A += bb * sAb + hh * sAh;
    B += bb * sBb + hh * sBh;
    C += bb * sCb + hh * sCh;

    const int row0 = blockIdx.y * 128;
    const int col0 = blockIdx.x * 128;

    const int tid  = threadIdx.x;
    const int warp = tid >> 5, lane = tid & 31;
    const int wm = warp >> 1, wn = warp & 1;
    const int g  = lane >> 2, t = lane & 3;

    const int lr = tid >> 3;     // 0..31
    const int kq = tid & 7;      // float4 slot along k
    const int nr = tid >> 5;     // 0..7
    const int nq = tid & 31;     // float4 slot along n

    float acc[2][8][4];
    #pragma unroll
    for (int i = 0; i < 2; i++)
        #pragma unroll
        for (int j = 0; j < 8; j++)
            #pragma unroll
            for (int q = 0; q < 4; q++) acc[i][j][q] = 0.f;

    int nk = K >> 5;
    if (causal & 1) {
        int cap = (row0 + 128) >> 5;
        if (cap < nk) nk = cap;
    }

    // As: [m][k] stride 36 ; Bs(BT): [n][k] stride 36 ; Bs(NN): [k][n] stride 136
#define ISSUE(KT)                                                                         \
    do {                                                                                  \
        if ((KT) < nk) {                                                                  \
            const int k0_ = (KT) * 32;                                                    \
            float* As_ = sm + ((KT) % 3) * STG_F;                                         \
            float* Bs_ = As_ + 4608;                                                      \
            _Pragma("unroll")                                                             \
            for (int i = 0; i < 4; i++) {                                                 \
                cp16(As_ + (i * 32 + lr) * 36 + kq * 4,                                   \
                     A + (long long)(row0 + i * 32 + lr) * lda + k0_ + kq * 4);           \
                if (BT)                                                                   \
                    cp16(Bs_ + (i * 32 + lr) * 36 + kq * 4,                               \
                         B + (long long)(col0 + i * 32 + lr) * ldb + k0_ + kq * 4);       \
                else                                                                      \
                    cp16(Bs_ + (i * 8 + nr) * 136 + nq * 4,                               \
                         B + (long long)(k0_ + i * 8 + nr) * ldb + col0 + nq * 4);        \
            }                                                                             \
        }                                                                                 \
        asm volatile("cp.async.commit_group;\n");                                        \
    } while (0)

    ISSUE(0);
    ISSUE(1);

    for (int kt = 0; kt < nk; kt++) {
        ISSUE(kt + 2);
        asm volatile("cp.async.wait_group 2;\n" ::: "memory");
        __syncthreads();

        const float* As = sm + (kt % 3) * STG_F;
        const float* Bs = As + 4608;

        #pragma unroll
        for (int kk = 0; kk < 32; kk += 8) {
            unsigned af[2][4], bf[8][2];
            #pragma unroll
            for (int i = 0; i < 2; i++) {
                int r = wm * 32 + i * 16 + g;
                af[i][0] = __float_as_uint(As[r * 36 + kk + t]);
                af[i][1] = __float_as_uint(As[(r + 8) * 36 + kk + t]);
                af[i][2] = __float_as_uint(As[r * 36 + kk + t + 4]);
                af[i][3] = __float_as_uint(As[(r + 8) * 36 + kk + t + 4]);
            }
            #pragma unroll
            for (int j = 0; j < 8; j++) {
                int c = wn * 64 + j * 8 + g;
                if (BT) {
                    bf[j][0] = __float_as_uint(Bs[c * 36 + kk + t]);
                    bf[j][1] = __float_as_uint(Bs[c * 36 + kk + t + 4]);
                } else {
                    bf[j][0] = __float_as_uint(Bs[(kk + t) * 136 + c]);
                    bf[j][1] = __float_as_uint(Bs[(kk + t + 4) * 136 + c]);
                }
            }
            #pragma unroll
            for (int i = 0; i < 2; i++)
                #pragma unroll
                for (int j = 0; j < 8; j++)
                    mma_tf32(acc[i][j], af[i], bf[j]);
        }
        __syncthreads();
    }
#undef ISSUE

    // Epilogue
    #pragma unroll
    for (int i = 0; i < 2; i++) {
        long long r0 = row0 + wm * 32 + i * 16 + g;
        #pragma unroll
        for (int j = 0; j < 8; j++) {
            int cc = col0 + wn * 64 + j * 8 + 2 * t;
            float v0 = acc[i][j][0], v1 = acc[i][j][1];
            float v2 = acc[i][j][2], v3 = acc[i][j][3];
            if (rnd) { v0 = ftf32(v0); v1 = ftf32(v1); v2 = ftf32(v2); v3 = ftf32(v3); }
            *(float2*)(C + r0 * ldc + cc)       = make_float2(v0, v1);
            *(float2*)(C + (r0 + 8) * ldc + cc) = make_float2(v2, v3);
        }
    }
}

// ---------------------------------------------------------------------------
// Elementwise round-to-tf32
// ---------------------------------------------------------------------------
__global__ void round_tf32_kernel(const float* __restrict__ in, float* __restrict__ out, int n4)
{
    int i = blockIdx.x * 256 + threadIdx.x;
    if (i >= n4) return;
    float4 v = ((const float4*)in)[i];
    v.x = ftf32(v.x); v.y = ftf32(v.y); v.z = ftf32(v.z); v.w = ftf32(v.w);
    ((float4*)out)[i] = v;
}

// ---------------------------------------------------------------------------
// SIMT SGEMM fallback (only the tiny c_kr projection, full fp32)
// ---------------------------------------------------------------------------
__global__ void sgemm64(const float* __restrict__ A, const float* __restrict__ B,
                        float* __restrict__ C,
                        int M, int N, int K, int lda, int ldb, int ldc)
{
    const int row0 = blockIdx.y * 64;
    const int col0 = blockIdx.x * 64;

    __shared__ float As[16][68];
    __shared__ float Bs[16][68];

    const int tid = threadIdx.x;
    const int tx  = tid & 15;
    const int ty  = tid >> 4;
    const int ar = tid >> 2;
    const int ak = (tid & 3) * 4;

    float acc[4][4] = {};

    for (int k0 = 0; k0 < K; k0 += 16) {
        float4 av = *(const float4*)(A + (long long)(row0 + ar) * lda + (k0 + ak));
        As[ak + 0][ar] = av.x;
        As[ak + 1][ar] = av.y;
        As[ak + 2][ar] = av.z;
        As[ak + 3][ar] = av.w;
        float4 bv = *(const float4*)(B + (long long)(col0 + ar) * ldb + (k0 + ak)); // B^T
        Bs[ak + 0][ar] = bv.x;
        Bs[ak + 1][ar] = bv.y;
        Bs[ak + 2][ar] = bv.z;
        Bs[ak + 3][ar] = bv.w;
        __syncthreads();

        #pragma unroll
        for (int kk = 0; kk < 16; kk++) {
            float4 a4 = *(const float4*)&As[kk][ty * 4];
            float4 b4 = *(const float4*)&Bs[kk][tx * 4];
            float aa[4] = {a4.x, a4.y, a4.z, a4.w};
            float bbv[4] = {b4.x, b4.y, b4.z, b4.w};
            #pragma unroll
            for (int i = 0; i < 4; i++)
                #pragma unroll
                for (int j = 0; j < 4; j++)
                    acc[i][j] += aa[i] * bbv[j];
        }
        __syncthreads();
    }

    #pragma unroll
    for (int i = 0; i < 4; i++)
        #pragma unroll
        for (int j = 0; j < 4; j++)
            C[(long long)(row0 + ty * 4 + i) * ldc + (col0 + tx * 4 + j)] = acc[i][j];
}

// ---------------------------------------------------------------------------
// RoPE kernels (outputs tf32-rounded, written into concatenated buffers)
// ---------------------------------------------------------------------------
__global__ void rope_q_kernel(const float* __restrict__ in, float* __restrict__ qcbuf,
                              const float* __restrict__ cosp, const float* __restrict__ sinp)
{
    int j = blockIdx.x * blockDim.x + threadIdx.x;
    if (j >= B_ * T_ * NH_ * (DHR_ / 2)) return;
    int i = j & 31;
    int h = (j >> 5) & 15;
    int t = (j >> 9) & 2047;
    int b = j >> 20;
    float c = cosp[t * 32 + i];
    float s = sinp[t * 32 + i];
    float re = in[2 * j], im = in[2 * j + 1];
    long long base = ((long long)(b * NH_ + h) * T_ + t) * KCAT + 512 + 2 * i;
    qcbuf[base]     = ftf32(re * c - im * s);
    qcbuf[base + 1] = ftf32(re * s + im * c);
}

__global__ void rope_k_kernel(const float* __restrict__ in, float* __restrict__ ckvbuf,
                              const float* __restrict__ cosp, const float* __restrict__ sinp)
{
    int j = blockIdx.x * blockDim.x + threadIdx.x;
    if (j >= B_ * T_ * (DHR_ / 2)) return;
    int i = j & 31;
    int t = (j >> 5) & 2047;
    int b = j >> 16;
    float c = cosp[t * 32 + i];
    float s = sinp[t * 32 + i];
    float re = in[2 * j], im = in[2 * j + 1];
    long long base = ((long long)b * T_ + t) * KCAT + 512 + 2 * i;
    ckvbuf[base]     = ftf32(re * c - im * s);
    ckvbuf[base + 1] = ftf32(re * s + im * c);
}

// ---------------------------------------------------------------------------
// Causal softmax, in-place, tf32-rounded output. One block per row.
// Writes cols [0, ceil128(t+1)) — exactly what the capped y GEMM reads.
// ---------------------------------------------------------------------------
__global__ void softmax_causal_kernel(float* __restrict__ S)
{
    const float scale = 0.07216878364870323f;   // 1/sqrt(192)
    long long row = blockIdx.x;
    int t = (int)(row % T_);
    int limit = ((t >> 7) + 1) << 7;            // multiple of 128 covering t
    float* p = S + row * (long long)T_;
    int tid = threadIdx.x;

    float v[8];
    float m = -3.0e38f;
    #pragma unroll
    for (int j = 0; j < 8; j++) {
        int i = tid + j * 256;
        float x = -3.0e38f;
        if (i <= t) x = p[i] * scale;
        v[j] = x;
        m = fmaxf(m, x);
    }

    __shared__ float red[256];
    red[tid] = m;
    __syncthreads();
    for (int s = 128; s > 0; s >>= 1) {
        if (tid < s) red[tid] = fmaxf(red[tid], red[tid + s]);
        __syncthreads();
    }
    m = red[0];
    __syncthreads();

    float sum = 0.f;
    #pragma unroll
    for (int j = 0; j < 8; j++) {
        int i = tid + j * 256;
        float e = (i <= t) ? __expf(v[j] - m) : 0.f;
        v[j] = e;
        sum += e;
    }
    red[tid] = sum;
    __syncthreads();
    for (int s = 128; s > 0; s >>= 1) {
        if (tid < s) red[tid] += red[tid + s];
        __syncthreads();
    }
    float inv = 1.0f / red[0];

    #pragma unroll
    for (int j = 0; j < 8; j++) {
        int i = tid + j * 256;
        if (i < limit) p[i] = ftf32(v[j] * inv);
    }
}

// ---------------------------------------------------------------------------
// Host
// ---------------------------------------------------------------------------
#define SMEM_BYTES (3 * STG_F * 4)   // 110592

static inline void launch_tf32(const float* A, const float* B, float* C,
                               int M, int N, int K, int lda, int ldb, int ldc,
                               int batches, int HB,
                               long long sAb, long long sAh,
                               long long sBb, long long sBh,
                               long long sCb, long long sCh,
                               int BT, int rnd, int causal)
{
    dim3 grid(N / 128, M / 128, batches);
    tf32gemm<<<grid, 256, SMEM_BYTES>>>(A, B, C, K, lda, ldb, ldc, HB,
                                        sAb, sAh, sBb, sBh, sCb, sCh, BT, rnd, causal);
}

static inline void round_tf32(const float* in, float* out, long long n)
{
    int n4 = (int)(n / 4);
    round_tf32_kernel<<<(n4 + 255) / 256, 256>>>(in, out, n4);
}

extern "C" void kernel_launch(void* const* d_in, const int* in_sizes, int n_in,
                              void* d_out, int out_size)
{
    (void)in_sizes; (void)n_in; (void)out_size;
    const float* x     = (const float*)d_in[0];
    const float* cosp  = (const float*)d_in[1];
    const float* sinp  = (const float*)d_in[2];
    const float* W_dq  = (const float*)d_in[3];
    const float* W_uq  = (const float*)d_in[4];
    const float* W_dkv = (const float*)d_in[5];
    const float* W_uk  = (const float*)d_in[6];
    const float* W_uv  = (const float*)d_in[7];
    const float* W_qr  = (const float*)d_in[8];
    const float* W_kr  = (const float*)d_in[9];
    const float* W_o   = (const float*)d_in[10];
    float* y = (float*)d_out;

    static int smem_set = 0;
    if (!smem_set) {
        cudaFuncSetAttribute(tf32gemm, cudaFuncAttributeMaxDynamicSharedMemorySize, SMEM_BYTES);
        smem_set = 1;
    }

    float *xt, *wdq, *wuq, *wdkv, *wuk, *wuv, *wqr, *wo;
    float *cq, *ckv, *keff, *Rt, *qc, *cqr, *ckr, *S, *V;
    cudaGetSymbolAddress((void**)&xt,   g_xt);
    cudaGetSymbolAddress((void**)&wdq,  g_wdq);
    cudaGetSymbolAddress((void**)&wuq,  g_wuq);
    cudaGetSymbolAddress((void**)&wdkv, g_wdkv);
    cudaGetSymbolAddress((void**)&wuk,  g_wuk);
    cudaGetSymbolAddress((void**)&wuv,  g_wuv);
    cudaGetSymbolAddress((void**)&wqr,  g_wqr);
    cudaGetSymbolAddress((void**)&wo,   g_wo);
    cudaGetSymbolAddress((void**)&cq,   g_cq);
    cudaGetSymbolAddress((void**)&ckv,  g_ckv);
    cudaGetSymbolAddress((void**)&keff, g_keff);
    cudaGetSymbolAddress((void**)&Rt,   g_Rt);
    cudaGetSymbolAddress((void**)&qc,   g_qc);
    cudaGetSymbolAddress((void**)&cqr,  g_cqr);
    cudaGetSymbolAddress((void**)&ckr,  g_ckr);
    cudaGetSymbolAddress((void**)&S,    g_S);
    cudaGetSymbolAddress((void**)&V,    g_V);

    const long long TT    = (long long)T_ * T_;
    const long long T512  = (long long)T_ * 512;
    const long long TKC   = (long long)T_ * KCAT;
    const long long TC    = (long long)T_ * C_;

    // 0) tf32-round raw inputs
    round_tf32(x,     xt,   (long long)B_*T_*C_);
    round_tf32(W_dq,  wdq,  (long long)NLQ_*C_);
    round_tf32(W_uq,  wuq,  (long long)C_*NLQ_);
    round_tf32(W_dkv, wdkv, (long long)NLKV_*C_);
    round_tf32(W_uk,  wuk,  (long long)C_*NLKV_);
    round_tf32(W_uv,  wuv,  (long long)C_*NLKV_);
    round_tf32(W_qr,  wqr,  (long long)NH_*DHR_*NLQ_);
    round_tf32(W_o,   wo,   (long long)C_*C_);

    // 1) c_q = x @ W_dq^T   [4096,512]   (rounded out)
    launch_tf32(xt, wdq, cq, B_*T_, NLQ_, C_, C_, C_, NLQ_,
                1, 1, 0,0, 0,0, 0,0, 1, 1, 0);
    // 2) c_kv = x @ W_dkv^T [4096,512] -> ckv buffer (ldc=576, rounded)
    launch_tf32(xt, wdkv, ckv, B_*T_, NLKV_, C_, C_, C_, KCAT,
                1, 1, 0,0, 0,0, 0,0, 1, 1, 0);
    // 3) k_eff[h] (16 batched, 512x512x128, rounded)
    launch_tf32(wuq, wuk, keff, NLQ_, NLKV_, HS_, C_, NLKV_, NLKV_,
                NH_, NH_, 0, HS_, 0, (long long)HS_*NLKV_, 0, (long long)NLQ_*NLKV_, 0, 1, 0);
    // 4) Rt = W_o @ W_uv    [2048,512]   (rounded)
    launch_tf32(wo, wuv, Rt, C_, NLKV_, C_, C_, NLKV_, NLKV_,
                1, 1, 0,0, 0,0, 0,0, 0, 1, 0);
    // 5) q_c[b,h] = c_q[b] @ k_eff[h] -> qc buffer (ldc=576, rounded)
    launch_tf32(cq, keff, qc, T_, NLKV_, NLQ_, NLQ_, NLKV_, KCAT,
                B_*NH_, NH_, T512, 0, 0, (long long)NLQ_*NLKV_,
                (long long)NH_*TKC, TKC, 0, 1, 0);
    // 6) c_qr = c_q @ W_qr^T [4096,1024] (rope rounds later)
    launch_tf32(cq, wqr, cqr, B_*T_, NH_*DHR_, NLQ_, NLQ_, NLQ_, NH_*DHR_,
                1, 1, 0,0, 0,0, 0,0, 1, 0, 0);
    // 7) q_r = rope(c_qr) -> qc buffer cols [512:576]
    {
        int n = B_ * T_ * NH_ * (DHR_ / 2);
        rope_q_kernel<<<(n + 255) / 256, 256>>>(cqr, qc, cosp, sinp);
    }
    // 8) c_kr = x @ W_kr^T  [4096,64] (SIMT, full fp32)
    {
        dim3 grid(DHR_ / 64, (B_*T_) / 64, 1);
        sgemm64<<<grid, 256>>>(x, W_kr, ckr, B_*T_, DHR_, C_, C_, C_, DHR_);
    }
    // 9) k_r = rope(c_kr) -> ckv buffer cols [512:576]
    {
        int n = B_ * T_ * (DHR_ / 2);
        rope_k_kernel<<<(n + 255) / 256, 256>>>(ckr, ckv, cosp, sinp);
    }
    // 10) S = [q_c|q_r] @ [c_kv|k_r]^T  (32 batched, 2048x2048x576, causal-skip)
    launch_tf32(qc, ckv, S, T_, T_, KCAT, KCAT, KCAT, T_,
                B_*NH_, NH_, (long long)NH_*TKC, TKC, TKC, 0,
                (long long)NH_*TT, TT, 1, 0, 2);
    // 11) V[b] = c_kv[b] @ Rt^T  (2 batched, 2048x2048x512, rounded)
    //     V[b,s,c] = sum_k ckv[b,s,k] * Rt[c,k]  — precomputed value matrix
    launch_tf32(ckv, Rt, V, T_, C_, NLKV_, KCAT, NLKV_, C_,
                B_, 1, TKC, 0, 0, 0, TC, 0, 1, 1, 0);
    // 12) causal softmax in place (rounded, trimmed to ceil128(t+1) cols)
    softmax_causal_kernel<<<B_*NH_*T_, 256>>>(S);
    // 13) y[b,:,h*128:] = P[b,h] @ V[b][:, h*128:(h+1)*128]
    //     (32 batched, 2048x128x2048, K capped at row0+128, NN B layout)
    launch_tf32(S, V, y, T_, HS_, T_, T_, C_, C_,
                B_*NH_, NH_, (long long)NH_*TT, TT, TC, HS_,
                TC, HS_, 0, 0, 1);
}